// round 13
// baseline (speedup 1.0000x reference)
#include <cuda_runtime.h>
#include <cuda_fp16.h>
#include <cstdint>

constexpr int B_ = 128, T_ = 1024, D_ = 512, H_ = 1024, G_ = 3072;
constexpr int NTC = 32;            // recurrence CTAs (one per 32 h-cols)
constexpr int NWK = 116;           // IG worker CTAs
constexpr int GRID = NTC + NWK;    // 148 = one full wave
constexpr int IGN = 64, IGNT = 48, TG = 4;
constexpr int NTILES = IGNT * (T_ / TG);   // 12288

// rec smem: 2 x (A 32K | W 24K) = 112K, TRANS 48K
constexpr int BUFSZ = 57344, AOFF = 0, WOFF = 32768, TROFF = 114688;
// ig smem (proven layout)
constexpr int I_WH = 0, I_WL = 65536, I_XH = 131072, I_XL = 163840;
constexpr int SMEM_DYN = 196608;

__device__ __align__(128) __half g_x_hi[(size_t)B_ * T_ * D_];
__device__ __align__(128) __half g_x_lo[(size_t)B_ * T_ * D_];
__device__ __align__(128) __half g_whh_hi[(size_t)G_ * H_];   // per-nt slab, chunked+swizzled
__device__ __align__(128) __half g_wih_hi[(size_t)G_ * D_];
__device__ __align__(128) __half g_wih_lo[(size_t)G_ * D_];
__device__ float g_IG[(size_t)T_ * B_ * G_];
__device__ __align__(128) __half g_h_hi[2][B_ * H_];
__device__ __align__(128) __half g_h_lo[2][B_ * H_];
__device__ unsigned int g_Hf[NTC][32];
__device__ unsigned int g_IGf[NTILES];

__device__ __forceinline__ uint32_t smem_u32(const void* p) {
    uint32_t a;
    asm("{ .reg .u64 t; cvta.to.shared.u64 t, %1; cvt.u32.u64 %0, t; }" : "=r"(a) : "l"(p));
    return a;
}
__device__ __forceinline__ void ldm4(uint32_t* r, uint32_t a) {
    asm volatile("ldmatrix.sync.aligned.m8n8.x4.shared.b16 {%0,%1,%2,%3}, [%4];"
                 : "=r"(r[0]), "=r"(r[1]), "=r"(r[2]), "=r"(r[3]) : "r"(a));
}
__device__ __forceinline__ void mma_f16(float* d, const uint32_t* a, uint32_t b0, uint32_t b1) {
    asm volatile(
        "mma.sync.aligned.m16n8k16.row.col.f32.f16.f16.f32 "
        "{%0,%1,%2,%3},{%4,%5,%6,%7},{%8,%9},{%0,%1,%2,%3};"
        : "+f"(d[0]), "+f"(d[1]), "+f"(d[2]), "+f"(d[3])
        : "r"(a[0]), "r"(a[1]), "r"(a[2]), "r"(a[3]), "r"(b0), "r"(b1));
}
__device__ __forceinline__ void cpa16(uint32_t s, const void* g) {
    asm volatile("cp.async.cg.shared.global [%0], [%1], 16;" :: "r"(s), "l"(g));
}
__device__ __forceinline__ void cp_commit() { asm volatile("cp.async.commit_group;" ::: "memory"); }
__device__ __forceinline__ void cp_wait0()  { asm volatile("cp.async.wait_group 0;" ::: "memory"); }
__device__ __forceinline__ void hsplit(float f, __half& hi, __half& lo) {
    hi = __float2half_rn(f);
    lo = __float2half_rn(f - __half2float(hi));
}
__device__ __forceinline__ void poll_ge(const unsigned int* p, unsigned int v) {
    unsigned int x;
    do {
        asm volatile("ld.acquire.gpu.global.u32 %0, [%1];" : "=r"(x) : "l"(p) : "memory");
    } while (x < v);
}
__device__ __forceinline__ void rel_st(unsigned int* p, unsigned int v) {
    asm volatile("st.release.gpu.global.u32 [%0], %1;" :: "l"(p), "r"(v) : "memory");
}
__device__ __forceinline__ void mbar_init(uint32_t a, uint32_t cnt) {
    asm volatile("mbarrier.init.shared.b64 [%0], %1;" :: "r"(a), "r"(cnt) : "memory");
}
__device__ __forceinline__ void mbar_expect(uint32_t a, uint32_t bytes) {
    asm volatile("mbarrier.arrive.expect_tx.shared.b64 _, [%0], %1;" :: "r"(a), "r"(bytes) : "memory");
}
__device__ __forceinline__ void mbar_wait(uint32_t a, uint32_t parity) {
    asm volatile(
        "{\n\t.reg .pred P;\n\tLAB_%=:\n\t"
        "mbarrier.try_wait.parity.shared.b64 P, [%0], %1;\n\t"
        "@!P bra LAB_%=;\n\t}"
        :: "r"(a), "r"(parity) : "memory");
}
__device__ __forceinline__ void bulk_g2s(uint32_t smem, const void* g, uint32_t bytes, uint32_t mbar) {
    asm volatile(
        "cp.async.bulk.shared::cluster.global.mbarrier::complete_tx::bytes [%0], [%1], %2, [%3];"
        :: "r"(smem), "l"(g), "r"(bytes), "r"(mbar) : "memory");
}
__device__ __forceinline__ void st2(uint32_t a, float x, float y) {
    asm volatile("st.shared.v2.f32 [%0], {%1,%2};" :: "r"(a), "f"(x), "f"(y) : "memory");
}
__device__ __forceinline__ uint32_t hoff(int b, int j) {
    return ((uint32_t)(j >> 6) << 13) + ((uint32_t)b << 6)
         + ((uint32_t)(((j >> 3) & 7) ^ (b & 7)) << 3) + (uint32_t)(j & 7);
}

__global__ void init_kernel() {
    unsigned idx = blockIdx.x * blockDim.x + threadIdx.x;
    for (unsigned i = idx; i < (unsigned)(NTC * 32); i += gridDim.x * blockDim.x)
        (&g_Hf[0][0])[i] = 0u;
    for (unsigned i = idx; i < (unsigned)NTILES; i += gridDim.x * blockDim.x)
        g_IGf[i] = 0u;
    for (unsigned i = idx; i < (unsigned)(B_ * H_); i += gridDim.x * blockDim.x) {
        g_h_hi[0][i] = __float2half(0.0f);
        g_h_lo[0][i] = __float2half(0.0f);
    }
}
__global__ void split_w(const float* __restrict__ whh, const float* __restrict__ wih) {
    size_t i = (size_t)blockIdx.x * blockDim.x + threadIdx.x;
    size_t nhh = (size_t)G_ * H_;
    if (i < nhh) {
        // whh hi-only -> per-nt slab: 16 k-chunks(64) x [96 rows x 64 halves swizzled]
        __half hi = __float2half_rn(whh[i]);
        int ghrow = (int)(i >> 10), k = (int)(i & 1023);
        int gate = ghrow >> 10, hrow = ghrow & 1023;
        int nt = hrow >> 5, nc = gate * 32 + (hrow & 31);
        int kt = k >> 6, kk6 = k & 63;
        size_t dst = (size_t)nt * 98304 + kt * 6144 + nc * 64
                   + (((kk6 >> 3) ^ (nc & 7)) << 3) + (k & 7);
        g_whh_hi[dst] = hi;
    } else if (i < nhh + (size_t)G_ * D_) {
        size_t j = i - nhh;
        __half hi, lo; hsplit(wih[j], hi, lo);
        g_wih_hi[j] = hi; g_wih_lo[j] = lo;
    }
}
__global__ void split_x(const float* __restrict__ x) {
    size_t i = (size_t)blockIdx.x * blockDim.x + threadIdx.x;
    size_t n2 = (size_t)B_ * T_ * D_ / 2;
    if (i < n2) {
        float2 v = reinterpret_cast<const float2*>(x)[i];
        __half h0, l0, h1, l1;
        hsplit(v.x, h0, l0); hsplit(v.y, h1, l1);
        reinterpret_cast<__half2*>(g_x_hi)[i] = __halves2half2(h0, h1);
        reinterpret_cast<__half2*>(g_x_lo)[i] = __halves2half2(l0, l1);
    }
}

// ---------------------------------------------------------------------------
// Fused kernel: CTAs [0,32) = persistent GRU recurrence (full-K, no k-split);
// CTAs [32,148) = IG workers (proven 3-term tile GEMM) setting per-tile flags.
// ---------------------------------------------------------------------------
__global__ __launch_bounds__(256, 1) void gru_fused(const float* __restrict__ bn,
                                                    const float* __restrict__ bias) {
    extern __shared__ __align__(1024) char smem[];
    __shared__ __align__(16) unsigned long long s_bar[2];
    const uint32_t sb = smem_u32(smem);
    const int tid = threadIdx.x;
    const int lane = tid & 31, warp = tid >> 5;
    const int wm = warp >> 1, wn = warp & 1;
    const int g8 = lane >> 3, r8 = lane & 7;
    const int gq = lane >> 2, cq = lane & 3;

    if ((int)blockIdx.x >= NTC) {
        // ================= IG worker =================
        const int w = blockIdx.x - NTC;
        int rowA[2], rowB[2];
        rowA[0] = wm * 32 + r8 + (g8 & 1) * 8; rowA[1] = rowA[0] + 16;
        rowB[0] = wn * 32 + r8 + (g8 >> 1) * 8; rowB[1] = rowB[0] + 16;
        const int cbA = g8 >> 1, cbB = g8 & 1;

        for (int tile = w; tile < NTILES; tile += NWK) {
            const int by = tile / IGNT, bx = tile - by * IGNT, n0 = bx * IGN;
            for (int idx = tid; idx < 64 * 64; idx += 256) {
                int row = idx >> 6, c = idx & 63;
                size_t src = (size_t)(n0 + row) * D_ + c * 8;
                uint32_t off = ((row * 64 + (c ^ (row & 7))) << 4);
                cpa16(sb + I_WH + off, g_wih_hi + src);
                cpa16(sb + I_WL + off, g_wih_lo + src);
            }
            cp_commit(); cp_wait0();
            __syncthreads();

            for (int tt = 0; tt < TG; tt++) {
                const int t = by * TG + tt;
                float acc[2][4][4];
#pragma unroll
                for (int i = 0; i < 2; i++)
#pragma unroll
                    for (int j = 0; j < 4; j++)
#pragma unroll
                        for (int q = 0; q < 4; q++) acc[i][j][q] = 0.0f;

                for (int kc = 0; kc < 4; kc++) {
                    __syncthreads();
                    for (int idx = tid; idx < 128 * 16; idx += 256) {
                        int row = idx >> 4, c = idx & 15;
                        size_t src = ((size_t)row * T_ + t) * D_ + kc * 128 + c * 8;
                        uint32_t off = ((row * 16 + (c ^ (row & 7))) << 4);
                        cpa16(sb + I_XH + off, g_x_hi + src);
                        cpa16(sb + I_XL + off, g_x_lo + src);
                    }
                    cp_commit(); cp_wait0();
                    __syncthreads();

#pragma unroll
                    for (int kk = 0; kk < 8; kk++) {
                        const int kk2 = kk * 2;
                        uint32_t ah[2][4], al[2][4];
#pragma unroll
                        for (int i = 0; i < 2; i++) {
                            uint32_t off = ((rowA[i] * 16 + ((kk2 + cbA) ^ (rowA[i] & 7))) << 4);
                            ldm4(ah[i], sb + I_XH + off);
                            ldm4(al[i], sb + I_XL + off);
                        }
                        const int kkc = kc * 16 + kk2;
                        uint32_t bh[2][4], bl[2][4];
#pragma unroll
                        for (int j = 0; j < 2; j++) {
                            uint32_t off = ((rowB[j] * 64 + ((kkc + cbB) ^ (rowB[j] & 7))) << 4);
                            ldm4(bh[j], sb + I_WH + off);
                            ldm4(bl[j], sb + I_WL + off);
                        }
#pragma unroll
                        for (int i = 0; i < 2; i++)
#pragma unroll
                            for (int j = 0; j < 2; j++) {
                                mma_f16(acc[i][2 * j],     ah[i], bh[j][0], bh[j][1]);
                                mma_f16(acc[i][2 * j + 1], ah[i], bh[j][2], bh[j][3]);
                                mma_f16(acc[i][2 * j],     ah[i], bl[j][0], bl[j][1]);
                                mma_f16(acc[i][2 * j + 1], ah[i], bl[j][2], bl[j][3]);
                                mma_f16(acc[i][2 * j],     al[i], bh[j][0], bh[j][1]);
                                mma_f16(acc[i][2 * j + 1], al[i], bh[j][2], bh[j][3]);
                            }
                    }
                }
#pragma unroll
                for (int i = 0; i < 2; i++)
#pragma unroll
                    for (int j = 0; j < 4; j++) {
                        int row = wm * 32 + i * 16 + gq;
                        int gcol = n0 + wn * 32 + j * 8 + 2 * cq;
                        float b0 = __ldg(&bias[gcol]), b1 = __ldg(&bias[gcol + 1]);
                        size_t o0 = ((size_t)t * B_ + row) * G_ + gcol;
                        *reinterpret_cast<float2*>(&g_IG[o0]) =
                            make_float2(acc[i][j][0] + b0, acc[i][j][1] + b1);
                        *reinterpret_cast<float2*>(&g_IG[o0 + (size_t)8 * G_]) =
                            make_float2(acc[i][j][2] + b0, acc[i][j][3] + b1);
                    }
            }
            __syncthreads();
            if (tid == 0) rel_st(&g_IGf[tile], 1u);
        }
        return;
    }

    // ================= recurrence CTA =================
    const int nt = blockIdx.x;
    const uint32_t barB[2] = { smem_u32(&s_bar[0]), smem_u32(&s_bar[1]) };
    if (tid == 0) { mbar_init(barB[0], 1); mbar_init(barB[1], 1); }
    __syncthreads();

    int rowA[2], rowB[3];
    rowA[0] = wm * 32 + r8 + (g8 & 1) * 8; rowA[1] = rowA[0] + 16;
    rowB[0] = wn * 48 + r8 + (g8 >> 1) * 8; rowB[1] = rowB[0] + 16; rowB[2] = rowB[0] + 32;
    const int cbA = g8 >> 1, cbB = g8 & 1;
    const __half* wslab = g_whh_hi + (size_t)nt * 98304;
    const int jl = (tid & 7) * 4, hc = nt * 32 + jl;
    const int bxa = (tid - 32) * 16 + (nt >> 1);       // for tid 32..34

    for (int t = 0; t < T_; t++) {
        if (tid < 32) poll_ge(&g_Hf[tid][0], (unsigned)t);
        else if (tid < 35) poll_ge(&g_IGf[(t >> 2) * IGNT + bxa], 1u);
        __syncthreads();

        const __half* hhi = g_h_hi[t & 1];
        if (tid == 0) {
#pragma unroll
            for (int c = 0; c < 2; c++) {
                mbar_expect(barB[c], 57344);
                bulk_g2s(sb + c * BUFSZ + AOFF, hhi + (size_t)c * 16384, 32768, barB[c]);
                bulk_g2s(sb + c * BUFSZ + WOFF, wslab + (size_t)c * 12288, 24576, barB[c]);
            }
        }

        float acc[2][6][4];
#pragma unroll
        for (int i = 0; i < 2; i++)
#pragma unroll
            for (int j = 0; j < 6; j++)
#pragma unroll
                for (int q = 0; q < 4; q++) acc[i][j][q] = 0.0f;

        for (int c = 0; c < 8; c++) {
            const uint32_t bufA = sb + (c & 1) * BUFSZ + AOFF;
            const uint32_t bufW = sb + (c & 1) * BUFSZ + WOFF;
            mbar_wait(barB[c & 1], (uint32_t)((c >> 1) & 1));
#pragma unroll
            for (int kk = 0; kk < 8; kk++) {
                uint32_t ah[2][4];
                const int ca = kk * 2 + cbA;
#pragma unroll
                for (int i = 0; i < 2; i++) {
                    uint32_t off = (uint32_t)(ca >> 3) * 16384 + ((uint32_t)rowA[i] << 7)
                                 + ((uint32_t)((ca & 7) ^ (rowA[i] & 7)) << 4);
                    ldm4(ah[i], bufA + off);
                }
                uint32_t bh[3][4];
                const int cb = kk * 2 + cbB;
#pragma unroll
                for (int j = 0; j < 3; j++) {
                    uint32_t off = (uint32_t)(cb >> 3) * 12288 + ((uint32_t)rowB[j] << 7)
                                 + ((uint32_t)((cb & 7) ^ (rowB[j] & 7)) << 4);
                    ldm4(bh[j], bufW + off);
                }
#pragma unroll
                for (int i = 0; i < 2; i++)
#pragma unroll
                    for (int j = 0; j < 3; j++) {
                        mma_f16(acc[i][2 * j],     ah[i], bh[j][0], bh[j][1]);
                        mma_f16(acc[i][2 * j + 1], ah[i], bh[j][2], bh[j][3]);
                    }
            }
            if (c < 6) {
                __syncthreads();   // all warps done with buffer (c&1)
                if (tid == 0) {
                    mbar_expect(barB[c & 1], 57344);
                    bulk_g2s(sb + (c & 1) * BUFSZ + AOFF, hhi + (size_t)(c + 2) * 16384, 32768, barB[c & 1]);
                    bulk_g2s(sb + (c & 1) * BUFSZ + WOFF, wslab + (size_t)(c + 2) * 12288, 24576, barB[c & 1]);
                }
            }
        }

        // transpose partials into TRANS (swizzled [128 rows][96 cols])
#pragma unroll
        for (int i = 0; i < 2; i++)
#pragma unroll
            for (int j = 0; j < 6; j++) {
                int row = wm * 32 + i * 16 + gq;
                int nc = wn * 48 + j * 8 + 2 * cq;
                uint32_t a0 = sb + TROFF + (uint32_t)row * 384
                            + ((uint32_t)((nc >> 2) ^ (row & 7)) << 4) + (nc & 3) * 4;
                uint32_t a1 = sb + TROFF + (uint32_t)(row + 8) * 384
                            + ((uint32_t)((nc >> 2) ^ ((row + 8) & 7)) << 4) + (nc & 3) * 4;
                st2(a0, acc[i][j][0], acc[i][j][1]);
                st2(a1, acc[i][j][2], acc[i][j][3]);
            }
        __syncthreads();

        // gating: all 128 rows x own 32 h-cols (4 iterations of 32 rows)
        const __half* hlo = g_h_lo[t & 1];
        __half* dhi = g_h_hi[(t + 1) & 1];
        __half* dlo = g_h_lo[(t + 1) & 1];
#pragma unroll
        for (int it = 0; it < 4; it++) {
            const int b = (tid >> 3) + it * 32;
            const char* tb = smem + TROFF + b * 384;
            const int sw = b & 7;
            float4 pr = *reinterpret_cast<const float4*>(tb + ((((tid & 7))      ^ sw) << 4));
            float4 pz = *reinterpret_cast<const float4*>(tb + (((8 + (tid & 7))  ^ sw) << 4));
            float4 pn = *reinterpret_cast<const float4*>(tb + (((16 + (tid & 7)) ^ sw) << 4));
            const float* igt = g_IG + ((size_t)t * B_ + b) * G_;
            float4 igr = *reinterpret_cast<const float4*>(igt + hc);
            float4 igz = *reinterpret_cast<const float4*>(igt + H_ + hc);
            float4 ign = *reinterpret_cast<const float4*>(igt + 2 * H_ + hc);
            float4 bnv = *reinterpret_cast<const float4*>(bn + hc);
            uint32_t ho = hoff(b, hc);
            uint2 rh = *reinterpret_cast<const uint2*>(hhi + ho);
            uint2 rl = *reinterpret_cast<const uint2*>(hlo + ho);
            float2 hh0 = __half22float2(*reinterpret_cast<__half2*>(&rh.x));
            float2 hh1 = __half22float2(*reinterpret_cast<__half2*>(&rh.y));
            float2 hl0 = __half22float2(*reinterpret_cast<__half2*>(&rl.x));
            float2 hl1 = __half22float2(*reinterpret_cast<__half2*>(&rl.y));
            float hold[4] = { hh0.x + hl0.x, hh0.y + hl0.y, hh1.x + hl1.x, hh1.y + hl1.y };
            float hgr[4] = { pr.x, pr.y, pr.z, pr.w };
            float hgz[4] = { pz.x, pz.y, pz.z, pz.w };
            float hgn[4] = { pn.x, pn.y, pn.z, pn.w };
            float igrv[4] = { igr.x, igr.y, igr.z, igr.w };
            float igzv[4] = { igz.x, igz.y, igz.z, igz.w };
            float ignv[4] = { ign.x, ign.y, ign.z, ign.w };
            float bnvv[4] = { bnv.x, bnv.y, bnv.z, bnv.w };
            __half nhi[4], nlo[4];
#pragma unroll
            for (int q = 0; q < 4; q++) {
                float r = 1.0f / (1.0f + expf(-(igrv[q] + hgr[q])));
                float z = 1.0f / (1.0f + expf(-(igzv[q] + hgz[q])));
                float nn = tanhf(ignv[q] + r * (hgn[q] + bnvv[q]));
                float hnew = nn + z * (hold[q] - nn);
                hsplit(hnew, nhi[q], nlo[q]);
            }
            uint2 wh, wl;
            __half2 t0 = __halves2half2(nhi[0], nhi[1]);
            __half2 t1 = __halves2half2(nhi[2], nhi[3]);
            __half2 t2 = __halves2half2(nlo[0], nlo[1]);
            __half2 t3 = __halves2half2(nlo[2], nlo[3]);
            wh.x = *reinterpret_cast<uint32_t*>(&t0); wh.y = *reinterpret_cast<uint32_t*>(&t1);
            wl.x = *reinterpret_cast<uint32_t*>(&t2); wl.y = *reinterpret_cast<uint32_t*>(&t3);
            *reinterpret_cast<uint2*>(dhi + ho) = wh;
            *reinterpret_cast<uint2*>(dlo + ho) = wl;
        }
        __syncthreads();
        if (tid == 0) rel_st(&g_Hf[nt][0], (unsigned)(t + 1));
    }
}

__global__ void out_kernel(const float* __restrict__ w_out,
                           const float* __restrict__ b_out,
                           float* __restrict__ out) {
    __shared__ float red[256];
    int b = blockIdx.x;
    float s = 0.0f;
    for (int j = threadIdx.x; j < H_; j += blockDim.x) {
        uint32_t ho = hoff(b, j);
        float h = __half2float(g_h_hi[0][ho]) + __half2float(g_h_lo[0][ho]);
        s += h * w_out[j];
    }
    red[threadIdx.x] = s;
    __syncthreads();
    for (int off = 128; off > 0; off >>= 1) {
        if (threadIdx.x < off) red[threadIdx.x] += red[threadIdx.x + off];
        __syncthreads();
    }
    if (threadIdx.x == 0) out[b] = red[0] + b_out[0];
}

extern "C" void kernel_launch(void* const* d_in, const int* in_sizes, int n_in,
                              void* d_out, int out_size) {
    const float* x     = (const float*)d_in[0];
    const float* w_ih  = (const float*)d_in[1];
    const float* w_hh  = (const float*)d_in[2];
    const float* b     = (const float*)d_in[3];
    const float* bn    = (const float*)d_in[4];
    const float* w_out = (const float*)d_in[5];
    const float* b_out = (const float*)d_in[6];
    float* out = (float*)d_out;

    cudaFuncSetAttribute(gru_fused, cudaFuncAttributeMaxDynamicSharedMemorySize, SMEM_DYN);

    init_kernel<<<128, 256>>>();
    size_t nsplit = (size_t)G_ * H_ + (size_t)G_ * D_;
    split_w<<<(unsigned)((nsplit + 255) / 256), 256>>>(w_hh, w_ih);
    split_x<<<(unsigned)(((size_t)B_ * T_ * D_ / 2 + 255) / 256), 256>>>(x);

    gru_fused<<<GRID, 256, SMEM_DYN>>>(bn, b);

    out_kernel<<<B_, 256>>>(w_out, b_out, out);
}

// round 14
// speedup vs baseline: 1.6542x; 1.6542x over previous
#include <cuda_runtime.h>
#include <cuda_fp16.h>
#include <cstdint>

constexpr int B_ = 128, T_ = 1024, D_ = 512, H_ = 1024, G_ = 3072;
constexpr int NT = 32, KS = 4, NB = NT * KS;
constexpr int IGN = 64, IGNT = G_ / IGN, TG = 4;

// gru smem: W_hi 48KB | A 4x16KB | PRECV 48KB = 160KB
constexpr int R_WH = 0;
constexpr int AB   = 49152;
constexpr int PRECV = 114688;
constexpr int R_SMEM = 163840;
// ig smem: W hi 64KB | W lo 64KB | X hi 32KB = 160KB
constexpr int I_WH = 0, I_WL = 65536, I_XH = 131072;
constexpr int I_SMEM = 163840;

__device__ __align__(128) __half g_x_hi[(size_t)B_ * T_ * D_];
__device__ __align__(128) __half g_whh_hi[(size_t)G_ * H_];    // per-(nt,ks) slab
__device__ __align__(128) __half g_wih_hi[(size_t)G_ * D_];
__device__ __align__(128) __half g_wih_lo[(size_t)G_ * D_];
__device__ float g_IG[(size_t)T_ * B_ * G_];
__device__ __align__(128) __half g_h_hi[2][B_ * H_];
__device__ __align__(128) __half g_h_lo[2][B_ * H_];
__device__ unsigned int g_Hf[NT][KS][32];

__device__ __forceinline__ uint32_t smem_u32(const void* p) {
    uint32_t a;
    asm("{ .reg .u64 t; cvta.to.shared.u64 t, %1; cvt.u32.u64 %0, t; }" : "=r"(a) : "l"(p));
    return a;
}
__device__ __forceinline__ void ldm4(uint32_t* r, uint32_t a) {
    asm volatile("ldmatrix.sync.aligned.m8n8.x4.shared.b16 {%0,%1,%2,%3}, [%4];"
                 : "=r"(r[0]), "=r"(r[1]), "=r"(r[2]), "=r"(r[3]) : "r"(a));
}
__device__ __forceinline__ void mma_f16(float* d, const uint32_t* a, uint32_t b0, uint32_t b1) {
    asm volatile(
        "mma.sync.aligned.m16n8k16.row.col.f32.f16.f16.f32 "
        "{%0,%1,%2,%3},{%4,%5,%6,%7},{%8,%9},{%0,%1,%2,%3};"
        : "+f"(d[0]), "+f"(d[1]), "+f"(d[2]), "+f"(d[3])
        : "r"(a[0]), "r"(a[1]), "r"(a[2]), "r"(a[3]), "r"(b0), "r"(b1));
}
__device__ __forceinline__ void cpa16(uint32_t s, const void* g) {
    asm volatile("cp.async.cg.shared.global [%0], [%1], 16;" :: "r"(s), "l"(g));
}
__device__ __forceinline__ void cp_commit() { asm volatile("cp.async.commit_group;" ::: "memory"); }
__device__ __forceinline__ void cp_wait0()  { asm volatile("cp.async.wait_group 0;" ::: "memory"); }
__device__ __forceinline__ void hsplit(float f, __half& hi, __half& lo) {
    hi = __float2half_rn(f);
    lo = __float2half_rn(f - __half2float(hi));
}
__device__ __forceinline__ void poll_ge(const unsigned int* p, unsigned int v) {
    unsigned int x;
    do {
        asm volatile("ld.acquire.gpu.global.u32 %0, [%1];" : "=r"(x) : "l"(p) : "memory");
    } while (x < v);
}
__device__ __forceinline__ void rel_st(unsigned int* p, unsigned int v) {
    asm volatile("st.release.gpu.global.u32 [%0], %1;" :: "l"(p), "r"(v) : "memory");
}
__device__ __forceinline__ void mbar_init(uint32_t a, uint32_t cnt) {
    asm volatile("mbarrier.init.shared.b64 [%0], %1;" :: "r"(a), "r"(cnt) : "memory");
}
__device__ __forceinline__ void mbar_expect(uint32_t a, uint32_t bytes) {
    asm volatile("mbarrier.arrive.expect_tx.shared.b64 _, [%0], %1;" :: "r"(a), "r"(bytes) : "memory");
}
__device__ __forceinline__ void mbar_wait(uint32_t a, uint32_t parity) {
    asm volatile(
        "{\n\t.reg .pred P;\n\tLAB_%=:\n\t"
        "mbarrier.try_wait.parity.shared.b64 P, [%0], %1;\n\t"
        "@!P bra LAB_%=;\n\t}"
        :: "r"(a), "r"(parity) : "memory");
}
__device__ __forceinline__ void bulk_g2s(uint32_t smem, const void* g, uint32_t bytes, uint32_t mbar) {
    asm volatile(
        "cp.async.bulk.shared::cluster.global.mbarrier::complete_tx::bytes [%0], [%1], %2, [%3];"
        :: "r"(smem), "l"(g), "r"(bytes), "r"(mbar) : "memory");
}
__device__ __forceinline__ uint32_t mapa_u32(uint32_t laddr, uint32_t rank) {
    uint32_t r;
    asm("mapa.shared::cluster.u32 %0, %1, %2;" : "=r"(r) : "r"(laddr), "r"(rank));
    return r;
}
__device__ __forceinline__ void stc64(uint32_t a, float x, float y) {
    asm volatile("{ .reg .b64 v; mov.b64 v, {%1,%2}; st.shared::cluster.b64 [%0], v; }"
                 :: "r"(a), "f"(x), "f"(y) : "memory");
}
#define CARR()  asm volatile("barrier.cluster.arrive.aligned;" ::: "memory")
#define CWAIT() asm volatile("barrier.cluster.wait.aligned;" ::: "memory")

__device__ __forceinline__ uint32_t hoff(int b, int j) {
    return ((uint32_t)(j >> 6) << 13) + ((uint32_t)b << 6)
         + ((uint32_t)(((j >> 3) & 7) ^ (b & 7)) << 3) + (uint32_t)(j & 7);
}

__global__ void init_kernel() {
    unsigned idx = blockIdx.x * blockDim.x + threadIdx.x;
    for (unsigned i = idx; i < (unsigned)(NT * KS * 32); i += gridDim.x * blockDim.x)
        (&g_Hf[0][0][0])[i] = 0u;
    for (unsigned i = idx; i < (unsigned)(B_ * H_); i += gridDim.x * blockDim.x) {
        g_h_hi[0][i] = __float2half(0.0f);
        g_h_lo[0][i] = __float2half(0.0f);
    }
}
__global__ void split_w(const float* __restrict__ whh, const float* __restrict__ wih) {
    size_t i = (size_t)blockIdx.x * blockDim.x + threadIdx.x;
    size_t nhh = (size_t)G_ * H_;
    if (i < nhh) {
        __half hi = __float2half_rn(whh[i]);
        int ghrow = (int)(i >> 10), k = (int)(i & 1023);
        int gate = ghrow >> 10, hrow = ghrow & 1023;
        int nt = hrow >> 5, nc = gate * 32 + (hrow & 31);
        int ks = k >> 8, kk = k & 255;
        int swz = ((kk >> 3) & 7) ^ (nc & 7);
        size_t dst = (size_t)(nt * KS + ks) * 24576 + (kk >> 6) * 6144 + nc * 64 + swz * 8 + (kk & 7);
        g_whh_hi[dst] = hi;
    } else if (i < nhh + (size_t)G_ * D_) {
        size_t j = i - nhh;
        __half hi, lo; hsplit(wih[j], hi, lo);
        g_wih_hi[j] = hi; g_wih_lo[j] = lo;
    }
}
__global__ void split_x(const float* __restrict__ x) {
    size_t i = (size_t)blockIdx.x * blockDim.x + threadIdx.x;
    size_t n2 = (size_t)B_ * T_ * D_ / 2;
    if (i < n2) {
        float2 v = reinterpret_cast<const float2*>(x)[i];
        reinterpret_cast<__half2*>(g_x_hi)[i] =
            __halves2half2(__float2half_rn(v.x), __float2half_rn(v.y));
    }
}

// IG GEMM, 2-term (x_hi * (W_hi + W_lo)): grid (48, 256)
__global__ __launch_bounds__(256, 1) void ig_gemm(const float* __restrict__ bias) {
    extern __shared__ __align__(1024) char smem[];
    const uint32_t sb = smem_u32(smem);
    const int tid = threadIdx.x;
    const int lane = tid & 31, warp = tid >> 5;
    const int wm = warp >> 1, wn = warp & 1;
    const int g8 = lane >> 3, r8 = lane & 7;
    const int gq = lane >> 2, cq = lane & 3;
    const int n0 = blockIdx.x * IGN;

    int rowA[2], rowB[2];
    rowA[0] = wm * 32 + r8 + (g8 & 1) * 8; rowA[1] = rowA[0] + 16;
    rowB[0] = wn * 32 + r8 + (g8 >> 1) * 8; rowB[1] = rowB[0] + 16;
    const int cbA = g8 >> 1, cbB = g8 & 1;

    for (int idx = tid; idx < 64 * 64; idx += 256) {
        int row = idx >> 6, c = idx & 63;
        size_t src = (size_t)(n0 + row) * D_ + c * 8;
        uint32_t off = ((row * 64 + (c ^ (row & 7))) << 4);
        cpa16(sb + I_WH + off, g_wih_hi + src);
        cpa16(sb + I_WL + off, g_wih_lo + src);
    }
    cp_commit(); cp_wait0();
    __syncthreads();

    for (int tt = 0; tt < TG; tt++) {
        const int t = blockIdx.y * TG + tt;
        float acc[2][4][4];
#pragma unroll
        for (int i = 0; i < 2; i++)
#pragma unroll
            for (int j = 0; j < 4; j++)
#pragma unroll
                for (int q = 0; q < 4; q++) acc[i][j][q] = 0.0f;

        for (int kc = 0; kc < 4; kc++) {
            __syncthreads();
            for (int idx = tid; idx < 128 * 16; idx += 256) {
                int row = idx >> 4, c = idx & 15;
                size_t src = ((size_t)row * T_ + t) * D_ + kc * 128 + c * 8;
                uint32_t off = ((row * 16 + (c ^ (row & 7))) << 4);
                cpa16(sb + I_XH + off, g_x_hi + src);
            }
            cp_commit(); cp_wait0();
            __syncthreads();

#pragma unroll
            for (int kk = 0; kk < 8; kk++) {
                const int kk2 = kk * 2;
                uint32_t ah[2][4];
#pragma unroll
                for (int i = 0; i < 2; i++) {
                    uint32_t off = ((rowA[i] * 16 + ((kk2 + cbA) ^ (rowA[i] & 7))) << 4);
                    ldm4(ah[i], sb + I_XH + off);
                }
                const int kkc = kc * 16 + kk2;
                uint32_t bh[2][4], bl[2][4];
#pragma unroll
                for (int j = 0; j < 2; j++) {
                    uint32_t off = ((rowB[j] * 64 + ((kkc + cbB) ^ (rowB[j] & 7))) << 4);
                    ldm4(bh[j], sb + I_WH + off);
                    ldm4(bl[j], sb + I_WL + off);
                }
#pragma unroll
                for (int i = 0; i < 2; i++)
#pragma unroll
                    for (int j = 0; j < 2; j++) {
                        mma_f16(acc[i][2 * j],     ah[i], bh[j][0], bh[j][1]);
                        mma_f16(acc[i][2 * j + 1], ah[i], bh[j][2], bh[j][3]);
                        mma_f16(acc[i][2 * j],     ah[i], bl[j][0], bl[j][1]);
                        mma_f16(acc[i][2 * j + 1], ah[i], bl[j][2], bl[j][3]);
                    }
            }
        }

#pragma unroll
        for (int i = 0; i < 2; i++)
#pragma unroll
            for (int j = 0; j < 4; j++) {
                int row = wm * 32 + i * 16 + gq;
                int gcol = n0 + wn * 32 + j * 8 + 2 * cq;
                float b0 = __ldg(&bias[gcol]), b1 = __ldg(&bias[gcol + 1]);
                size_t o0 = ((size_t)t * B_ + row) * G_ + gcol;
                *reinterpret_cast<float2*>(&g_IG[o0]) =
                    make_float2(acc[i][j][0] + b0, acc[i][j][1] + b1);
                *reinterpret_cast<float2*>(&g_IG[o0 + (size_t)8 * G_]) =
                    make_float2(acc[i][j][2] + b0, acc[i][j][3] + b1);
            }
    }
}

// ---------------------------------------------------------------------------
// Persistent GRU recurrence (round-12 protocol), 1-term MMA (h_hi * W_hi).
// ---------------------------------------------------------------------------
__global__ __launch_bounds__(256, 1) __cluster_dims__(4, 1, 1)
void gru_persist(const float* __restrict__ bn) {
    extern __shared__ __align__(1024) char smem[];
    __shared__ __align__(16) unsigned long long s_bar[5];
    const uint32_t sb = smem_u32(smem);
    uint32_t barC[4];
#pragma unroll
    for (int c = 0; c < 4; c++) barC[c] = smem_u32(&s_bar[c]);
    const uint32_t barW = smem_u32(&s_bar[4]);

    const int tid = threadIdx.x;
    const int lane = tid & 31, warp = tid >> 5;
    const int wm = warp >> 1, wn = warp & 1;
    const int g8 = lane >> 3, r8 = lane & 7;
    const int gq = lane >> 2, cq = lane & 3;

    uint32_t rank;
    asm("mov.u32 %0, %%cluster_ctarank;" : "=r"(rank));
    const int ks = (int)rank;
    const int nt = blockIdx.x >> 2;
    const int slab = nt * KS + ks;

    int rowA[2], rowB[3];
    rowA[0] = wm * 32 + r8 + (g8 & 1) * 8; rowA[1] = rowA[0] + 16;
    rowB[0] = wn * 48 + r8 + (g8 >> 1) * 8; rowB[1] = rowB[0] + 16; rowB[2] = rowB[0] + 32;
    const int cbA = g8 >> 1, cbB = g8 & 1;

    if (tid == 0) {
#pragma unroll
        for (int c = 0; c < 4; c++) mbar_init(barC[c], 1);
        mbar_init(barW, 1);
    }
    __syncthreads();
    if (tid == 0) {
        mbar_expect(barW, 49152);
        bulk_g2s(sb + R_WH, g_whh_hi + (size_t)slab * 24576, 49152, barW);
    }
    mbar_wait(barW, 0);
    __syncthreads();

    const int grl = tid >> 3;
    const int gc  = (tid & 7) * 4;
    const int hc  = nt * 32 + gc;
    const uint32_t rbase = mapa_u32(sb + PRECV + (uint32_t)ks * 12288, (uint32_t)wm);

    for (int t = 0; t < T_; t++) {
        if (tid < 32) poll_ge(&g_Hf[ks * 8 + (tid >> 2)][tid & 3][0], (unsigned)t);
        __syncthreads();

        const __half* hhi = g_h_hi[t & 1];
        const __half* hlo = g_h_lo[t & 1];

        if (tid == 0) {
#pragma unroll
            for (int c = 0; c < 4; c++) {
                mbar_expect(barC[c], 16384);
                bulk_g2s(sb + AB + c * 16384, hhi + (size_t)(ks * 4 + c) * 8192, 16384, barC[c]);
            }
        }

        float acc[2][6][4];
#pragma unroll
        for (int i = 0; i < 2; i++)
#pragma unroll
            for (int j = 0; j < 6; j++)
#pragma unroll
                for (int q = 0; q < 4; q++) acc[i][j][q] = 0.0f;

#pragma unroll
        for (int kc = 0; kc < 4; kc++) {
            const uint32_t buf = sb + AB + kc * 16384;
            mbar_wait(barC[kc], (uint32_t)(t & 1));
#pragma unroll
            for (int kk = 0; kk < 4; kk++) {
                const int kk2 = kk * 2;
                uint32_t ah[2][4];
#pragma unroll
                for (int i = 0; i < 2; i++) {
                    int c = kk2 + cbA;
                    uint32_t off = ((uint32_t)rowA[i] << 7) + ((uint32_t)(c ^ (rowA[i] & 7)) << 4);
                    ldm4(ah[i], buf + off);
                }
                uint32_t bh[3][4];
#pragma unroll
                for (int j = 0; j < 3; j++) {
                    int cg = kc * 8 + kk2 + cbB;
                    uint32_t off = (uint32_t)kc * 12288 + ((uint32_t)rowB[j] << 7)
                                 + ((uint32_t)((cg & 7) ^ (rowB[j] & 7)) << 4);
                    ldm4(bh[j], sb + R_WH + off);
                }
#pragma unroll
                for (int i = 0; i < 2; i++)
#pragma unroll
                    for (int j = 0; j < 3; j++) {
                        mma_f16(acc[i][2 * j],     ah[i], bh[j][0], bh[j][1]);
                        mma_f16(acc[i][2 * j + 1], ah[i], bh[j][2], bh[j][3]);
                    }
            }
        }

        const int grow = ks * 32 + grl;
        const float* ig_t = g_IG + ((size_t)t * B_ + grow) * G_;
        float4 igr = *reinterpret_cast<const float4*>(ig_t + hc);
        float4 igz = *reinterpret_cast<const float4*>(ig_t + H_ + hc);
        float4 ign = *reinterpret_cast<const float4*>(ig_t + 2 * H_ + hc);
        float4 bnv = *reinterpret_cast<const float4*>(bn + hc);
        uint32_t ho = hoff(grow, hc);
        uint2 rh = *reinterpret_cast<const uint2*>(hhi + ho);
        uint2 rl = *reinterpret_cast<const uint2*>(hlo + ho);

        if (t) CWAIT();

#pragma unroll
        for (int i = 0; i < 2; i++) {
            int lr = i * 16 + gq;
#pragma unroll
            for (int j = 0; j < 6; j++) {
                int nc = wn * 48 + j * 8 + 2 * cq;
                uint32_t a = rbase + (uint32_t)lr * 384 + (uint32_t)nc * 4;
                stc64(a,           acc[i][j][0], acc[i][j][1]);
                stc64(a + 8 * 384, acc[i][j][2], acc[i][j][3]);
            }
        }
        CARR(); CWAIT();

        {
            float4 pr = make_float4(0.f, 0.f, 0.f, 0.f), pz = pr, pn = pr;
#pragma unroll
            for (int s = 0; s < KS; s++) {
                const char* base = smem + PRECV + s * 12288 + grl * 384;
                float4 a  = *reinterpret_cast<const float4*>(base + gc * 4);
                float4 bz = *reinterpret_cast<const float4*>(base + (32 + gc) * 4);
                float4 cn = *reinterpret_cast<const float4*>(base + (64 + gc) * 4);
                pr.x += a.x;  pr.y += a.y;  pr.z += a.z;  pr.w += a.w;
                pz.x += bz.x; pz.y += bz.y; pz.z += bz.z; pz.w += bz.w;
                pn.x += cn.x; pn.y += cn.y; pn.z += cn.z; pn.w += cn.w;
            }
            float2 hh0 = __half22float2(*reinterpret_cast<__half2*>(&rh.x));
            float2 hh1 = __half22float2(*reinterpret_cast<__half2*>(&rh.y));
            float2 hl0 = __half22float2(*reinterpret_cast<__half2*>(&rl.x));
            float2 hl1 = __half22float2(*reinterpret_cast<__half2*>(&rl.y));
            float hold[4] = { hh0.x + hl0.x, hh0.y + hl0.y, hh1.x + hl1.x, hh1.y + hl1.y };
            float hgr[4] = { pr.x, pr.y, pr.z, pr.w };
            float hgz[4] = { pz.x, pz.y, pz.z, pz.w };
            float hgn[4] = { pn.x, pn.y, pn.z, pn.w };
            float igrv[4] = { igr.x, igr.y, igr.z, igr.w };
            float igzv[4] = { igz.x, igz.y, igz.z, igz.w };
            float ignv[4] = { ign.x, ign.y, ign.z, ign.w };
            float bnvv[4] = { bnv.x, bnv.y, bnv.z, bnv.w };
            __half nhi[4], nlo[4];
#pragma unroll
            for (int q = 0; q < 4; q++) {
                float r = 1.0f / (1.0f + expf(-(igrv[q] + hgr[q])));
                float z = 1.0f / (1.0f + expf(-(igzv[q] + hgz[q])));
                float nn = tanhf(ignv[q] + r * (hgn[q] + bnvv[q]));
                float hnew = nn + z * (hold[q] - nn);
                hsplit(hnew, nhi[q], nlo[q]);
            }
            uint2 wh, wl;
            __half2 t0 = __halves2half2(nhi[0], nhi[1]);
            __half2 t1 = __halves2half2(nhi[2], nhi[3]);
            __half2 t2 = __halves2half2(nlo[0], nlo[1]);
            __half2 t3 = __halves2half2(nlo[2], nlo[3]);
            wh.x = *reinterpret_cast<uint32_t*>(&t0); wh.y = *reinterpret_cast<uint32_t*>(&t1);
            wl.x = *reinterpret_cast<uint32_t*>(&t2); wl.y = *reinterpret_cast<uint32_t*>(&t3);
            *reinterpret_cast<uint2*>(&g_h_hi[(t + 1) & 1][ho]) = wh;
            *reinterpret_cast<uint2*>(&g_h_lo[(t + 1) & 1][ho]) = wl;
        }
        __syncthreads();
        if (tid == 0) rel_st(&g_Hf[nt][ks][0], (unsigned)(t + 1));
        CARR();
    }
    CWAIT();
}

__global__ void out_kernel(const float* __restrict__ w_out,
                           const float* __restrict__ b_out,
                           float* __restrict__ out) {
    __shared__ float red[256];
    int b = blockIdx.x;
    float s = 0.0f;
    for (int j = threadIdx.x; j < H_; j += blockDim.x) {
        uint32_t ho = hoff(b, j);
        float h = __half2float(g_h_hi[0][ho]) + __half2float(g_h_lo[0][ho]);
        s += h * w_out[j];
    }
    red[threadIdx.x] = s;
    __syncthreads();
    for (int off = 128; off > 0; off >>= 1) {
        if (threadIdx.x < off) red[threadIdx.x] += red[threadIdx.x + off];
        __syncthreads();
    }
    if (threadIdx.x == 0) out[b] = red[0] + b_out[0];
}

extern "C" void kernel_launch(void* const* d_in, const int* in_sizes, int n_in,
                              void* d_out, int out_size) {
    const float* x     = (const float*)d_in[0];
    const float* w_ih  = (const float*)d_in[1];
    const float* w_hh  = (const float*)d_in[2];
    const float* b     = (const float*)d_in[3];
    const float* bn    = (const float*)d_in[4];
    const float* w_out = (const float*)d_in[5];
    const float* b_out = (const float*)d_in[6];
    float* out = (float*)d_out;

    cudaFuncSetAttribute(ig_gemm, cudaFuncAttributeMaxDynamicSharedMemorySize, I_SMEM);
    cudaFuncSetAttribute(gru_persist, cudaFuncAttributeMaxDynamicSharedMemorySize, R_SMEM);

    init_kernel<<<128, 256>>>();
    size_t nsplit = (size_t)G_ * H_ + (size_t)G_ * D_;
    split_w<<<(unsigned)((nsplit + 255) / 256), 256>>>(w_hh, w_ih);
    split_x<<<(unsigned)(((size_t)B_ * T_ * D_ / 2 + 255) / 256), 256>>>(x);

    dim3 gig(IGNT, T_ / TG);
    ig_gemm<<<gig, 256, I_SMEM>>>(b);

    gru_persist<<<NB, 256, R_SMEM>>>(bn);

    out_kernel<<<B_, 256>>>(w_out, b_out, out);
}

// round 16
// speedup vs baseline: 1.8371x; 1.1105x over previous
#include <cuda_runtime.h>
#include <cuda_fp16.h>
#include <cstdint>

constexpr int B_ = 128, T_ = 1024, D_ = 512, H_ = 1024, G_ = 3072;
constexpr int NT = 32, KS = 4, NB = NT * KS;
constexpr int IGN = 64, IGNT = G_ / IGN, TG = 4;

// gru smem: W_hi 48KB | A 4x16KB | PRECV 2 buffers x (4 slabs x 6144B) = 48KB
constexpr int R_WH = 0;
constexpr int AB    = 49152;
constexpr int PRECV = 114688;
constexpr int PRSLAB = 6144;          // one peer slab: 32 rows x 96 halves
constexpr int PRBUF  = 4 * PRSLAB;    // 24576
constexpr int R_SMEM = 163840;
// ig smem
constexpr int I_WH = 0, I_WL = 65536, I_XH = 131072;
constexpr int I_SMEM = 163840;

__device__ __align__(128) __half g_x_hi[(size_t)B_ * T_ * D_];
__device__ __align__(128) __half g_whh_hi[(size_t)G_ * H_];
__device__ __align__(128) __half g_wih_hi[(size_t)G_ * D_];
__device__ __align__(128) __half g_wih_lo[(size_t)G_ * D_];
__device__ float g_IG[(size_t)T_ * B_ * G_];
__device__ __align__(128) __half g_h_hi[2][B_ * H_];
__device__ __align__(128) __half g_h_lo[2][B_ * H_];
__device__ unsigned int g_Hf[NT][KS][32];

__device__ __forceinline__ uint32_t smem_u32(const void* p) {
    uint32_t a;
    asm("{ .reg .u64 t; cvta.to.shared.u64 t, %1; cvt.u32.u64 %0, t; }" : "=r"(a) : "l"(p));
    return a;
}
__device__ __forceinline__ void ldm4(uint32_t* r, uint32_t a) {
    asm volatile("ldmatrix.sync.aligned.m8n8.x4.shared.b16 {%0,%1,%2,%3}, [%4];"
                 : "=r"(r[0]), "=r"(r[1]), "=r"(r[2]), "=r"(r[3]) : "r"(a));
}
__device__ __forceinline__ void mma_f16(float* d, const uint32_t* a, uint32_t b0, uint32_t b1) {
    asm volatile(
        "mma.sync.aligned.m16n8k16.row.col.f32.f16.f16.f32 "
        "{%0,%1,%2,%3},{%4,%5,%6,%7},{%8,%9},{%0,%1,%2,%3};"
        : "+f"(d[0]), "+f"(d[1]), "+f"(d[2]), "+f"(d[3])
        : "r"(a[0]), "r"(a[1]), "r"(a[2]), "r"(a[3]), "r"(b0), "r"(b1));
}
__device__ __forceinline__ void cpa16(uint32_t s, const void* g) {
    asm volatile("cp.async.cg.shared.global [%0], [%1], 16;" :: "r"(s), "l"(g));
}
__device__ __forceinline__ void cp_commit() { asm volatile("cp.async.commit_group;" ::: "memory"); }
__device__ __forceinline__ void cp_wait0()  { asm volatile("cp.async.wait_group 0;" ::: "memory"); }
__device__ __forceinline__ void hsplit(float f, __half& hi, __half& lo) {
    hi = __float2half_rn(f);
    lo = __float2half_rn(f - __half2float(hi));
}
__device__ __forceinline__ void poll_ge(const unsigned int* p, unsigned int v) {
    unsigned int x;
    do {
        asm volatile("ld.acquire.gpu.global.u32 %0, [%1];" : "=r"(x) : "l"(p) : "memory");
    } while (x < v);
}
__device__ __forceinline__ void rel_st(unsigned int* p, unsigned int v) {
    asm volatile("st.release.gpu.global.u32 [%0], %1;" :: "l"(p), "r"(v) : "memory");
}
__device__ __forceinline__ void mbar_init(uint32_t a, uint32_t cnt) {
    asm volatile("mbarrier.init.shared.b64 [%0], %1;" :: "r"(a), "r"(cnt) : "memory");
}
__device__ __forceinline__ void mbar_expect(uint32_t a, uint32_t bytes) {
    asm volatile("mbarrier.arrive.expect_tx.shared.b64 _, [%0], %1;" :: "r"(a), "r"(bytes) : "memory");
}
__device__ __forceinline__ void mbar_wait(uint32_t a, uint32_t parity) {
    asm volatile(
        "{\n\t.reg .pred P;\n\tLAB_%=:\n\t"
        "mbarrier.try_wait.parity.shared.b64 P, [%0], %1;\n\t"
        "@!P bra LAB_%=;\n\t}"
        :: "r"(a), "r"(parity) : "memory");
}
__device__ __forceinline__ void bulk_g2s(uint32_t smem, const void* g, uint32_t bytes, uint32_t mbar) {
    asm volatile(
        "cp.async.bulk.shared::cluster.global.mbarrier::complete_tx::bytes [%0], [%1], %2, [%3];"
        :: "r"(smem), "l"(g), "r"(bytes), "r"(mbar) : "memory");
}
__device__ __forceinline__ uint32_t mapa_u32(uint32_t laddr, uint32_t rank) {
    uint32_t r;
    asm("mapa.shared::cluster.u32 %0, %1, %2;" : "=r"(r) : "r"(laddr), "r"(rank));
    return r;
}
// push 2 fp32 partials as half2 (4B) into peer smem
__device__ __forceinline__ void stc32h(uint32_t a, float x, float y) {
    __half2 h = __halves2half2(__float2half_rn(x), __float2half_rn(y));
    asm volatile("st.shared::cluster.b32 [%0], %1;"
                 :: "r"(a), "r"(*reinterpret_cast<uint32_t*>(&h)) : "memory");
}
#define CARR()  asm volatile("barrier.cluster.arrive.aligned;" ::: "memory")
#define CWAIT() asm volatile("barrier.cluster.wait.aligned;" ::: "memory")

__device__ __forceinline__ uint32_t hoff(int b, int j) {
    return ((uint32_t)(j >> 6) << 13) + ((uint32_t)b << 6)
         + ((uint32_t)(((j >> 3) & 7) ^ (b & 7)) << 3) + (uint32_t)(j & 7);
}

__global__ void init_kernel() {
    unsigned idx = blockIdx.x * blockDim.x + threadIdx.x;
    for (unsigned i = idx; i < (unsigned)(NT * KS * 32); i += gridDim.x * blockDim.x)
        (&g_Hf[0][0][0])[i] = 0u;
    for (unsigned i = idx; i < (unsigned)(B_ * H_); i += gridDim.x * blockDim.x) {
        g_h_hi[0][i] = __float2half(0.0f);
        g_h_lo[0][i] = __float2half(0.0f);
    }
}
__global__ void split_w(const float* __restrict__ whh, const float* __restrict__ wih) {
    size_t i = (size_t)blockIdx.x * blockDim.x + threadIdx.x;
    size_t nhh = (size_t)G_ * H_;
    if (i < nhh) {
        __half hi = __float2half_rn(whh[i]);
        int ghrow = (int)(i >> 10), k = (int)(i & 1023);
        int gate = ghrow >> 10, hrow = ghrow & 1023;
        int nt = hrow >> 5, nc = gate * 32 + (hrow & 31);
        int ks = k >> 8, kk = k & 255;
        int swz = ((kk >> 3) & 7) ^ (nc & 7);
        size_t dst = (size_t)(nt * KS + ks) * 24576 + (kk >> 6) * 6144 + nc * 64 + swz * 8 + (kk & 7);
        g_whh_hi[dst] = hi;
    } else if (i < nhh + (size_t)G_ * D_) {
        size_t j = i - nhh;
        __half hi, lo; hsplit(wih[j], hi, lo);
        g_wih_hi[j] = hi; g_wih_lo[j] = lo;
    }
}
__global__ void split_x(const float* __restrict__ x) {
    size_t i = (size_t)blockIdx.x * blockDim.x + threadIdx.x;
    size_t n2 = (size_t)B_ * T_ * D_ / 2;
    if (i < n2) {
        float2 v = reinterpret_cast<const float2*>(x)[i];
        reinterpret_cast<__half2*>(g_x_hi)[i] =
            __halves2half2(__float2half_rn(v.x), __float2half_rn(v.y));
    }
}

// IG GEMM, 2-term (proven round 14): grid (48, 256)
__global__ __launch_bounds__(256, 1) void ig_gemm(const float* __restrict__ bias) {
    extern __shared__ __align__(1024) char smem[];
    const uint32_t sb = smem_u32(smem);
    const int tid = threadIdx.x;
    const int lane = tid & 31, warp = tid >> 5;
    const int wm = warp >> 1, wn = warp & 1;
    const int g8 = lane >> 3, r8 = lane & 7;
    const int gq = lane >> 2, cq = lane & 3;
    const int n0 = blockIdx.x * IGN;

    int rowA[2], rowB[2];
    rowA[0] = wm * 32 + r8 + (g8 & 1) * 8; rowA[1] = rowA[0] + 16;
    rowB[0] = wn * 32 + r8 + (g8 >> 1) * 8; rowB[1] = rowB[0] + 16;
    const int cbA = g8 >> 1, cbB = g8 & 1;

    for (int idx = tid; idx < 64 * 64; idx += 256) {
        int row = idx >> 6, c = idx & 63;
        size_t src = (size_t)(n0 + row) * D_ + c * 8;
        uint32_t off = ((row * 64 + (c ^ (row & 7))) << 4);
        cpa16(sb + I_WH + off, g_wih_hi + src);
        cpa16(sb + I_WL + off, g_wih_lo + src);
    }
    cp_commit(); cp_wait0();
    __syncthreads();

    for (int tt = 0; tt < TG; tt++) {
        const int t = blockIdx.y * TG + tt;
        float acc[2][4][4];
#pragma unroll
        for (int i = 0; i < 2; i++)
#pragma unroll
            for (int j = 0; j < 4; j++)
#pragma unroll
                for (int q = 0; q < 4; q++) acc[i][j][q] = 0.0f;

        for (int kc = 0; kc < 4; kc++) {
            __syncthreads();
            for (int idx = tid; idx < 128 * 16; idx += 256) {
                int row = idx >> 4, c = idx & 15;
                size_t src = ((size_t)row * T_ + t) * D_ + kc * 128 + c * 8;
                uint32_t off = ((row * 16 + (c ^ (row & 7))) << 4);
                cpa16(sb + I_XH + off, g_x_hi + src);
            }
            cp_commit(); cp_wait0();
            __syncthreads();

#pragma unroll
            for (int kk = 0; kk < 8; kk++) {
                const int kk2 = kk * 2;
                uint32_t ah[2][4];
#pragma unroll
                for (int i = 0; i < 2; i++) {
                    uint32_t off = ((rowA[i] * 16 + ((kk2 + cbA) ^ (rowA[i] & 7))) << 4);
                    ldm4(ah[i], sb + I_XH + off);
                }
                const int kkc = kc * 16 + kk2;
                uint32_t bh[2][4], bl[2][4];
#pragma unroll
                for (int j = 0; j < 2; j++) {
                    uint32_t off = ((rowB[j] * 64 + ((kkc + cbB) ^ (rowB[j] & 7))) << 4);
                    ldm4(bh[j], sb + I_WH + off);
                    ldm4(bl[j], sb + I_WL + off);
                }
#pragma unroll
                for (int i = 0; i < 2; i++)
#pragma unroll
                    for (int j = 0; j < 2; j++) {
                        mma_f16(acc[i][2 * j],     ah[i], bh[j][0], bh[j][1]);
                        mma_f16(acc[i][2 * j + 1], ah[i], bh[j][2], bh[j][3]);
                        mma_f16(acc[i][2 * j],     ah[i], bl[j][0], bl[j][1]);
                        mma_f16(acc[i][2 * j + 1], ah[i], bl[j][2], bl[j][3]);
                    }
            }
        }

#pragma unroll
        for (int i = 0; i < 2; i++)
#pragma unroll
            for (int j = 0; j < 4; j++) {
                int row = wm * 32 + i * 16 + gq;
                int gcol = n0 + wn * 32 + j * 8 + 2 * cq;
                float b0 = __ldg(&bias[gcol]), b1 = __ldg(&bias[gcol + 1]);
                size_t o0 = ((size_t)t * B_ + row) * G_ + gcol;
                *reinterpret_cast<float2*>(&g_IG[o0]) =
                    make_float2(acc[i][j][0] + b0, acc[i][j][1] + b1);
                *reinterpret_cast<float2*>(&g_IG[o0 + (size_t)8 * G_]) =
                    make_float2(acc[i][j][2] + b0, acc[i][j][3] + b1);
            }
    }
}

// ---------------------------------------------------------------------------
// Persistent GRU recurrence: 1-term MMA, fp16 DSMEM partials, dual PRECV
// buffers (correct 6144B slab stride), single cluster barrier per step.
// ---------------------------------------------------------------------------
__global__ __launch_bounds__(256, 1) __cluster_dims__(4, 1, 1)
void gru_persist(const float* __restrict__ bn) {
    extern __shared__ __align__(1024) char smem[];
    __shared__ __align__(16) unsigned long long s_bar[5];
    const uint32_t sb = smem_u32(smem);
    uint32_t barC[4];
#pragma unroll
    for (int c = 0; c < 4; c++) barC[c] = smem_u32(&s_bar[c]);
    const uint32_t barW = smem_u32(&s_bar[4]);

    const int tid = threadIdx.x;
    const int lane = tid & 31, warp = tid >> 5;
    const int wm = warp >> 1, wn = warp & 1;
    const int g8 = lane >> 3, r8 = lane & 7;
    const int gq = lane >> 2, cq = lane & 3;

    uint32_t rank;
    asm("mov.u32 %0, %%cluster_ctarank;" : "=r"(rank));
    const int ks = (int)rank;
    const int nt = blockIdx.x >> 2;
    const int slab = nt * KS + ks;

    int rowA[2], rowB[3];
    rowA[0] = wm * 32 + r8 + (g8 & 1) * 8; rowA[1] = rowA[0] + 16;
    rowB[0] = wn * 48 + r8 + (g8 >> 1) * 8; rowB[1] = rowB[0] + 16; rowB[2] = rowB[0] + 32;
    const int cbA = g8 >> 1, cbB = g8 & 1;

    if (tid == 0) {
#pragma unroll
        for (int c = 0; c < 4; c++) mbar_init(barC[c], 1);
        mbar_init(barW, 1);
    }
    __syncthreads();
    if (tid == 0) {
        mbar_expect(barW, 49152);
        bulk_g2s(sb + R_WH, g_whh_hi + (size_t)slab * 24576, 49152, barW);
    }
    mbar_wait(barW, 0);
    __syncthreads();

    const int grl = tid >> 3;
    const int gc  = (tid & 7) * 4;
    const int hc  = nt * 32 + gc;
    // remote base (buffer 0) of MY slab (index = own ks) inside peer wm's PRECV
    const uint32_t rbase0 = mapa_u32(sb + PRECV + (uint32_t)ks * PRSLAB, (uint32_t)wm);

    for (int t = 0; t < T_; t++) {
        if (tid < 32) poll_ge(&g_Hf[ks * 8 + (tid >> 2)][tid & 3][0], (unsigned)t);
        __syncthreads();

        const __half* hhi = g_h_hi[t & 1];
        const __half* hlo = g_h_lo[t & 1];

        if (tid == 0) {
#pragma unroll
            for (int c = 0; c < 4; c++) {
                mbar_expect(barC[c], 16384);
                bulk_g2s(sb + AB + c * 16384, hhi + (size_t)(ks * 4 + c) * 8192, 16384, barC[c]);
            }
        }

        float acc[2][6][4];
#pragma unroll
        for (int i = 0; i < 2; i++)
#pragma unroll
            for (int j = 0; j < 6; j++)
#pragma unroll
                for (int q = 0; q < 4; q++) acc[i][j][q] = 0.0f;

#pragma unroll
        for (int kc = 0; kc < 4; kc++) {
            const uint32_t buf = sb + AB + kc * 16384;
            mbar_wait(barC[kc], (uint32_t)(t & 1));
#pragma unroll
            for (int kk = 0; kk < 4; kk++) {
                const int kk2 = kk * 2;
                uint32_t ah[2][4];
#pragma unroll
                for (int i = 0; i < 2; i++) {
                    int c = kk2 + cbA;
                    uint32_t off = ((uint32_t)rowA[i] << 7) + ((uint32_t)(c ^ (rowA[i] & 7)) << 4);
                    ldm4(ah[i], buf + off);
                }
                uint32_t bh[3][4];
#pragma unroll
                for (int j = 0; j < 3; j++) {
                    int cg = kc * 8 + kk2 + cbB;
                    uint32_t off = (uint32_t)kc * 12288 + ((uint32_t)rowB[j] << 7)
                                 + ((uint32_t)((cg & 7) ^ (rowB[j] & 7)) << 4);
                    ldm4(bh[j], sb + R_WH + off);
                }
#pragma unroll
                for (int i = 0; i < 2; i++)
#pragma unroll
                    for (int j = 0; j < 3; j++) {
                        mma_f16(acc[i][2 * j],     ah[i], bh[j][0], bh[j][1]);
                        mma_f16(acc[i][2 * j + 1], ah[i], bh[j][2], bh[j][3]);
                    }
            }
        }

        // prefetch gating operands
        const int grow = ks * 32 + grl;
        const float* ig_t = g_IG + ((size_t)t * B_ + grow) * G_;
        float4 igr = *reinterpret_cast<const float4*>(ig_t + hc);
        float4 igz = *reinterpret_cast<const float4*>(ig_t + H_ + hc);
        float4 ign = *reinterpret_cast<const float4*>(ig_t + 2 * H_ + hc);
        float4 bnv = *reinterpret_cast<const float4*>(bn + hc);
        uint32_t ho = hoff(grow, hc);
        uint2 rh = *reinterpret_cast<const uint2*>(hhi + ho);
        uint2 rl = *reinterpret_cast<const uint2*>(hlo + ho);

        // push fp16 partials into peer's PRECV buffer (t&1) — dual buffer, so
        // no WAR barrier (safety transitive through step t-1's barrier)
        const uint32_t rb = rbase0 + (uint32_t)(t & 1) * PRBUF;
#pragma unroll
        for (int i = 0; i < 2; i++) {
            int lr = i * 16 + gq;      // rows {0..7,16..23}; +8 covers the rest
#pragma unroll
            for (int j = 0; j < 6; j++) {
                int nc = wn * 48 + j * 8 + 2 * cq;
                uint32_t a = rb + (uint32_t)lr * 192 + (uint32_t)nc * 2;
                stc32h(a,           acc[i][j][0], acc[i][j][1]);
                stc32h(a + 8 * 192, acc[i][j][2], acc[i][j][3]);
            }
        }
        CARR(); CWAIT();   // pushes visible cluster-wide

        // gating
        {
            float pr[4] = {0, 0, 0, 0}, pz[4] = {0, 0, 0, 0}, pn[4] = {0, 0, 0, 0};
#pragma unroll
            for (int s = 0; s < KS; s++) {
                const char* base = smem + PRECV + (t & 1) * PRBUF + s * PRSLAB + grl * 192;
                uint2 ra = *reinterpret_cast<const uint2*>(base + gc * 2);
                uint2 rz = *reinterpret_cast<const uint2*>(base + 64 + gc * 2);
                uint2 rn = *reinterpret_cast<const uint2*>(base + 128 + gc * 2);
                float2 a0 = __half22float2(*reinterpret_cast<__half2*>(&ra.x));
                float2 a1 = __half22float2(*reinterpret_cast<__half2*>(&ra.y));
                float2 z0 = __half22float2(*reinterpret_cast<__half2*>(&rz.x));
                float2 z1 = __half22float2(*reinterpret_cast<__half2*>(&rz.y));
                float2 n0 = __half22float2(*reinterpret_cast<__half2*>(&rn.x));
                float2 n1 = __half22float2(*reinterpret_cast<__half2*>(&rn.y));
                pr[0] += a0.x; pr[1] += a0.y; pr[2] += a1.x; pr[3] += a1.y;
                pz[0] += z0.x; pz[1] += z0.y; pz[2] += z1.x; pz[3] += z1.y;
                pn[0] += n0.x; pn[1] += n0.y; pn[2] += n1.x; pn[3] += n1.y;
            }
            float2 hh0 = __half22float2(*reinterpret_cast<__half2*>(&rh.x));
            float2 hh1 = __half22float2(*reinterpret_cast<__half2*>(&rh.y));
            float2 hl0 = __half22float2(*reinterpret_cast<__half2*>(&rl.x));
            float2 hl1 = __half22float2(*reinterpret_cast<__half2*>(&rl.y));
            float hold[4] = { hh0.x + hl0.x, hh0.y + hl0.y, hh1.x + hl1.x, hh1.y + hl1.y };
            float igrv[4] = { igr.x, igr.y, igr.z, igr.w };
            float igzv[4] = { igz.x, igz.y, igz.z, igz.w };
            float ignv[4] = { ign.x, ign.y, ign.z, ign.w };
            float bnvv[4] = { bnv.x, bnv.y, bnv.z, bnv.w };
            __half nhi[4], nlo[4];
#pragma unroll
            for (int q = 0; q < 4; q++) {
                float r = 1.0f / (1.0f + expf(-(igrv[q] + pr[q])));
                float z = 1.0f / (1.0f + expf(-(igzv[q] + pz[q])));
                float nn = tanhf(ignv[q] + r * (pn[q] + bnvv[q]));
                float hnew = nn + z * (hold[q] - nn);
                hsplit(hnew, nhi[q], nlo[q]);
            }
            uint2 wh, wl;
            __half2 t0 = __halves2half2(nhi[0], nhi[1]);
            __half2 t1 = __halves2half2(nhi[2], nhi[3]);
            __half2 t2 = __halves2half2(nlo[0], nlo[1]);
            __half2 t3 = __halves2half2(nlo[2], nlo[3]);
            wh.x = *reinterpret_cast<uint32_t*>(&t0); wh.y = *reinterpret_cast<uint32_t*>(&t1);
            wl.x = *reinterpret_cast<uint32_t*>(&t2); wl.y = *reinterpret_cast<uint32_t*>(&t3);
            *reinterpret_cast<uint2*>(&g_h_hi[(t + 1) & 1][ho]) = wh;
            *reinterpret_cast<uint2*>(&g_h_lo[(t + 1) & 1][ho]) = wl;
        }
        __syncthreads();
        if (tid == 0) rel_st(&g_Hf[nt][ks][0], (unsigned)(t + 1));
    }
    // drain: no CTA may exit while peers still push into its smem
    CARR(); CWAIT();
}

__global__ void out_kernel(const float* __restrict__ w_out,
                           const float* __restrict__ b_out,
                           float* __restrict__ out) {
    __shared__ float red[256];
    int b = blockIdx.x;
    float s = 0.0f;
    for (int j = threadIdx.x; j < H_; j += blockDim.x) {
        uint32_t ho = hoff(b, j);
        float h = __half2float(g_h_hi[0][ho]) + __half2float(g_h_lo[0][ho]);
        s += h * w_out[j];
    }
    red[threadIdx.x] = s;
    __syncthreads();
    for (int off = 128; off > 0; off >>= 1) {
        if (threadIdx.x < off) red[threadIdx.x] += red[threadIdx.x + off];
        __syncthreads();
    }
    if (threadIdx.x == 0) out[b] = red[0] + b_out[0];
}

extern "C" void kernel_launch(void* const* d_in, const int* in_sizes, int n_in,
                              void* d_out, int out_size) {
    const float* x     = (const float*)d_in[0];
    const float* w_ih  = (const float*)d_in[1];
    const float* w_hh  = (const float*)d_in[2];
    const float* b     = (const float*)d_in[3];
    const float* bn    = (const float*)d_in[4];
    const float* w_out = (const float*)d_in[5];
    const float* b_out = (const float*)d_in[6];
    float* out = (float*)d_out;

    cudaFuncSetAttribute(ig_gemm, cudaFuncAttributeMaxDynamicSharedMemorySize, I_SMEM);
    cudaFuncSetAttribute(gru_persist, cudaFuncAttributeMaxDynamicSharedMemorySize, R_SMEM);

    init_kernel<<<128, 256>>>();
    size_t nsplit = (size_t)G_ * H_ + (size_t)G_ * D_;
    split_w<<<(unsigned)((nsplit + 255) / 256), 256>>>(w_hh, w_ih);
    split_x<<<(unsigned)(((size_t)B_ * T_ * D_ / 2 + 255) / 256), 256>>>(x);

    dim3 gig(IGNT, T_ / TG);
    ig_gemm<<<gig, 256, I_SMEM>>>(b);

    gru_persist<<<NB, 256, R_SMEM>>>(bn);

    out_kernel<<<B_, 256>>>(w_out, b_out, out);
}